// round 14
// baseline (speedup 1.0000x reference)
#include <cuda_runtime.h>
#include <math.h>

// Problem constants
#define NN        512
#define ROWS      256
#define BM        32
#define BN        32
#define BK        32
#define NTILES    128
#define KSPLIT    4
#define KCHUNK    128
#define THREADS   256

#define SAMPLE_ELEMS 131072
#define STD_BYTES    268435456ull        // 256 MB
// Diag entry i occupies bytes [i*2048, i*2048+2048) (i.e. row i of std_mat).
// Entries i < 114688 lie entirely in the first 224 MB.
#define DIAG_SPLIT   114688u
#define MSA_BYTES    234881024ull        // DIAG_SPLIT * 2048 = 224 MB
#define FIXB_BLOCKS  ((SAMPLE_ELEMS - DIAG_SPLIT) / THREADS)   // 64

// Split-K partial sums + scratch for tail-region softplus values
__device__ float g_pv[KSPLIT][ROWS][NN];
__device__ float g_pm[KSPLIT][ROWS][NN];
__device__ float g_sp[SAMPLE_ELEMS];

__global__ __launch_bounds__(THREADS)
void gemm_stage1(const float* __restrict__ x,
                 const float* __restrict__ W)
{
    __shared__ float Xs[BM][BK + 1];
    __shared__ float Wv[BN][BK + 1];
    __shared__ float Wm[BN][BK + 1];

    const int tile  = blockIdx.x & 127;
    const int chunk = blockIdx.x >> 7;
    const int bm    = tile >> 4;
    const int bn    = tile & 15;
    const int row0  = bm * BM;
    const int n0    = bn * BN;
    const int kbeg  = chunk * KCHUNK;

    const int tid = threadIdx.x;
    const int tx  = tid & 15;
    const int ty  = tid >> 4;
    const int rl  = ty * 2;
    const int nl  = tx * 2;

    const int lr = tid >> 3;
    const int lc = (tid & 7) * 4;

    float av[2][2] = {{0.f,0.f},{0.f,0.f}};
    float am[2][2] = {{0.f,0.f},{0.f,0.f}};

    for (int k0 = kbeg; k0 < kbeg + KCHUNK; k0 += BK) {
        float4 xv = *reinterpret_cast<const float4*>(&x[(size_t)(row0 + lr) * NN + k0 + lc]);
        Xs[lr][lc + 0] = xv.x; Xs[lr][lc + 1] = xv.y;
        Xs[lr][lc + 2] = xv.z; Xs[lr][lc + 3] = xv.w;

        float4 wv = *reinterpret_cast<const float4*>(&W[(size_t)(n0 + lr) * NN + k0 + lc]);
        Wv[lr][lc + 0] = wv.x; Wv[lr][lc + 1] = wv.y;
        Wv[lr][lc + 2] = wv.z; Wv[lr][lc + 3] = wv.w;

        float4 wm = *reinterpret_cast<const float4*>(&W[(size_t)(512 + n0 + lr) * NN + k0 + lc]);
        Wm[lr][lc + 0] = wm.x; Wm[lr][lc + 1] = wm.y;
        Wm[lr][lc + 2] = wm.z; Wm[lr][lc + 3] = wm.w;

        __syncthreads();

        #pragma unroll
        for (int kk = 0; kk < BK; kk++) {
            float x0 = Xs[rl][kk],     x1 = Xs[rl + 1][kk];
            float v0 = Wv[nl][kk],     v1 = Wv[nl + 1][kk];
            float m0 = Wm[nl][kk],     m1 = Wm[nl + 1][kk];
            av[0][0] += x0 * v0;  av[0][1] += x0 * v1;
            av[1][0] += x1 * v0;  av[1][1] += x1 * v1;
            am[0][0] += x0 * m0;  am[0][1] += x0 * m1;
            am[1][0] += x1 * m0;  am[1][1] += x1 * m1;
        }
        __syncthreads();
    }

    #pragma unroll
    for (int rr = 0; rr < 2; rr++) {
        #pragma unroll
        for (int nn = 0; nn < 2; nn++) {
            g_pv[chunk][row0 + rl + rr][n0 + nl + nn] = av[rr][nn];
            g_pm[chunk][row0 + rl + rr][n0 + nl + nn] = am[rr][nn];
        }
    }
}

// Combine partials -> sample, mu; diag written DIRECTLY for i < DIAG_SPLIT
// (region already zeroed by msetA), scratch for the 16384 tail entries.
__global__ __launch_bounds__(THREADS)
void combine_all(const float* __restrict__ b,
                 const float* __restrict__ eps,
                 float* __restrict__ out)
{
    float* __restrict__ outS = out;
    float* __restrict__ outM = out + SAMPLE_ELEMS;
    float* __restrict__ outD = out + 2 * SAMPLE_ELEMS;

    const unsigned i = blockIdx.x * THREADS + threadIdx.x;
    const unsigned r = i >> 9;
    const unsigned n = i & 511u;

    float v = ((g_pv[0][r][n] + g_pv[1][r][n]) + (g_pv[2][r][n] + g_pv[3][r][n])) + b[n];
    float m = ((g_pm[0][r][n] + g_pm[1][r][n]) + (g_pm[2][r][n] + g_pm[3][r][n])) + b[512 + n];
    float sp = (v > 20.f) ? v : log1pf(expf(v));

    outM[i] = m;
    outS[i] = m + sqrtf(sp) * eps[i];
    if (i < DIAG_SPLIT)
        outD[(size_t)i * NN + n] = sp;     // direct diagonal into zeroed phase-A region
    else
        g_sp[i] = sp;                      // tail scratch for fixupB
}

// Tail: scatter the last 16384 diagonal entries after phase-B fill
__global__ __launch_bounds__(THREADS)
void diag_fixup_tail(float* __restrict__ out)
{
    float* __restrict__ outD = out + 2 * SAMPLE_ELEMS;
    const unsigned i = DIAG_SPLIT + blockIdx.x * THREADS + threadIdx.x;
    outD[(size_t)i * NN + (i & 511u)] = g_sp[i];
}

extern "C" void kernel_launch(void* const* d_in, const int* in_sizes, int n_in,
                              void* d_out, int out_size)
{
    const float* x   = (const float*)d_in[0];
    const float* W   = (const float*)d_in[1];
    const float* b   = (const float*)d_in[2];
    const float* eps = (const float*)d_in[3];
    float* out = (float*)d_out;

    (void)in_sizes; (void)n_in; (void)out_size;

    // One-time resources, created on the first (correctness) call — before graph capture.
    static cudaStream_t s_cmp  = nullptr;
    static cudaEvent_t  e_fork = nullptr;
    static cudaEvent_t  e_msA  = nullptr;
    static cudaEvent_t  e_cmb  = nullptr;
    if (s_cmp == nullptr) {
        cudaStreamCreateWithFlags(&s_cmp, cudaStreamNonBlocking);
        cudaEventCreateWithFlags(&e_fork, cudaEventDisableTiming);
        cudaEventCreateWithFlags(&e_msA,  cudaEventDisableTiming);
        cudaEventCreateWithFlags(&e_cmb,  cudaEventDisableTiming);
    }

    char* std_base = reinterpret_cast<char*>(out + 2 * SAMPLE_ELEMS);

    // Fork compute branch
    cudaEventRecord(e_fork, 0);
    cudaStreamWaitEvent(s_cmp, e_fork, 0);

    // Compute branch: split-K GEMM (scratch partials only)
    gemm_stage1<<<NTILES * KSPLIT, THREADS, 0, s_cmp>>>(x, W);

    // Legacy stream: two-phase fill — 224 MB then 32 MB
    cudaMemsetAsync(std_base, 0, MSA_BYTES);
    cudaEventRecord(e_msA, 0);
    cudaMemsetAsync(std_base + MSA_BYTES, 0, STD_BYTES - MSA_BYTES);

    // Combine after gemm (stream order) + msetA (event): writes sample, mu,
    // direct diag for phase A, scratch for tail. Overlaps msetB.
    cudaStreamWaitEvent(s_cmp, e_msA, 0);
    combine_all<<<SAMPLE_ELEMS / THREADS, THREADS, 0, s_cmp>>>(b, eps, out);
    cudaEventRecord(e_cmb, s_cmp);

    // Join and tail fixup (16384 entries) on the legacy stream
    cudaStreamWaitEvent(0, e_cmb, 0);
    diag_fixup_tail<<<FIXB_BLOCKS, THREADS>>>(out);
}